// round 1
// baseline (speedup 1.0000x reference)
#include <cuda_runtime.h>
#include <cstddef>

// ---------------------------------------------------------------------------
// VQ-VAE forward, fp32. All heavy ops via one generic im2col-gather GEMM.
// Scratch in __device__ globals (no allocation). Graph-capturable: kernel
// launches only on the default stream.
// ---------------------------------------------------------------------------

#define HS 256
#define NE 512

// ---- scratch buffers ----
__device__ __align__(16) float g_h16[16777216];   // 256*256*16*16 (enc h1, reused for deconv1 out)
__device__ __align__(16) float g_h8[4194304];     // 256*256*8*8 (encoder latent path)
__device__ __align__(16) float g_t8[4194304];     // rmsnorm temp
__device__ __align__(16) float g_q[4194304];      // quantized latent / decoder path
__device__ __align__(16) float g_scores[8388608]; // 256*512*64 VQ dot products
__device__ __align__(16) float g_wp[1048576];     // deconv1 parity weights 4*256*256*4
__device__ __align__(16) float g_enorm[512];
__device__ __align__(16) float g_part[512];       // [0:256) vq loss partials, [256:512) rec loss

// ---------------------------------------------------------------------------
// Generic conv-as-GEMM: C[m, oc] = sum_k A_gather[m,k] * W[oc,k]
//   m -> (n, oh, ow); k -> (ic, kh, kw); ih = oh*stride - padh + kh
// Epilogue modes: 0 = plain, 1 = relu(acc+bias), 2 = res + relu(acc+bias)
// Output index: ((n*N + oc)*oHW + (oh*oscale+ooffh)*oW + (ow*oscale+ooffw))
// Requires: M % 64 == 0, N % 64 == 0, K % 16 == 0 (true for all ops here).
// ---------------------------------------------------------------------------
struct GemmP {
    const float* A; const float* W; const float* bias; const float* res; float* out;
    int M, N, K;
    int IC, KH, KW, IH, IW, OH, OW, stride, padh, padw;
    int oscale, ooffh, ooffw, oW, oHW;
    int mode;
};

__global__ __launch_bounds__(256) void conv_gemm(GemmP p) {
    __shared__ float As[16 * 64];
    __shared__ float Bs[16 * 68];
    __shared__ int rowBase[64];
    __shared__ int rowY[64];
    __shared__ int rowX[64];

    const int tid = threadIdx.x;
    const int bm = blockIdx.x * 64;
    const int bn = blockIdx.y * 64;

    if (tid < 64) {
        int m = bm + tid;
        int ohw = p.OH * p.OW;
        int n = m / ohw;
        int rem = m - n * ohw;
        int oh = rem / p.OW;
        int ow = rem - oh * p.OW;
        rowBase[tid] = n * p.IC * p.IH * p.IW;
        rowY[tid] = oh * p.stride - p.padh;
        rowX[tid] = ow * p.stride - p.padw;
    }
    __syncthreads();

    const int tr = tid >> 4;        // 0..15
    const int tc = tid & 15;        // 0..15
    float acc[4][4];
#pragma unroll
    for (int i = 0; i < 4; i++)
#pragma unroll
        for (int j = 0; j < 4; j++) acc[i][j] = 0.f;

    const int khkw = p.KH * p.KW;
    const int r = tid & 63;         // A row within tile
    const int jbase = tid >> 6;     // 0..3
    const int ocb = tid >> 2;       // 0..63 B row (oc)
    const int j0 = (tid & 3) << 2;  // 0,4,8,12
    const float* Wrow = p.W + (size_t)(bn + ocb) * p.K + j0;

    for (int k0 = 0; k0 < p.K; k0 += 16) {
        // --- A tile: gather 64 rows x 16 k ---
        const int rby = rowY[r], rbx = rowX[r], rbb = rowBase[r];
#pragma unroll
        for (int q = 0; q < 4; q++) {
            int j = jbase + q * 4;
            int k = k0 + j;
            int ic = k / khkw;
            int kk = k - ic * khkw;
            int kh = kk / p.KW;
            int kw = kk - kh * p.KW;
            int ih = rby + kh, iw = rbx + kw;
            float v = 0.f;
            if ((unsigned)ih < (unsigned)p.IH && (unsigned)iw < (unsigned)p.IW)
                v = p.A[rbb + (ic * p.IH + ih) * p.IW + iw];
            As[j * 64 + r] = v;
        }
        // --- B tile: 64 oc x 16 k, float4 loads ---
        float4 w4 = *(const float4*)(Wrow + k0);
        Bs[(j0 + 0) * 68 + ocb] = w4.x;
        Bs[(j0 + 1) * 68 + ocb] = w4.y;
        Bs[(j0 + 2) * 68 + ocb] = w4.z;
        Bs[(j0 + 3) * 68 + ocb] = w4.w;
        __syncthreads();

#pragma unroll
        for (int kk = 0; kk < 16; kk++) {
            float a[4], b[4];
#pragma unroll
            for (int i = 0; i < 4; i++) a[i] = As[kk * 64 + tr * 4 + i];
#pragma unroll
            for (int j = 0; j < 4; j++) b[j] = Bs[kk * 68 + tc * 4 + j];
#pragma unroll
            for (int i = 0; i < 4; i++)
#pragma unroll
                for (int j = 0; j < 4; j++) acc[i][j] += a[i] * b[j];
        }
        __syncthreads();
    }

    // --- epilogue ---
    const int ohw = p.OH * p.OW;
#pragma unroll
    for (int i = 0; i < 4; i++) {
        int m = bm + tr * 4 + i;
        int n = m / ohw;
        int rem = m - n * ohw;
        int oh = rem / p.OW;
        int ow = rem - oh * p.OW;
        int oy = oh * p.oscale + p.ooffh;
        int ox = ow * p.oscale + p.ooffw;
#pragma unroll
        for (int j = 0; j < 4; j++) {
            int oc = bn + tc * 4 + j;
            float v = acc[i][j];
            if (p.bias) v += p.bias[oc];
            if (p.mode >= 1) v = fmaxf(v, 0.f);
            size_t oi = ((size_t)(n * p.N + oc)) * p.oHW + oy * p.oW + ox;
            if (p.mode == 2) v += p.res[oi];
            p.out[oi] = v;
        }
    }
}

// ---------------------------------------------------------------------------
// RMSNorm over (C,H,W)=16384 per sample; weight shape (256,8,8) flattened.
// ---------------------------------------------------------------------------
__global__ __launch_bounds__(256) void rmsnorm_kernel(const float* __restrict__ in,
                                                      const float* __restrict__ w,
                                                      float* __restrict__ out) {
    const int n = blockIdx.x;
    const float* xp = in + (size_t)n * 16384;
    float s = 0.f;
    for (int i = threadIdx.x; i < 16384; i += 256) {
        float v = xp[i];
        s += v * v;
    }
    __shared__ float sh[256];
    sh[threadIdx.x] = s;
    __syncthreads();
    for (int st = 128; st > 0; st >>= 1) {
        if (threadIdx.x < st) sh[threadIdx.x] += sh[threadIdx.x + st];
        __syncthreads();
    }
    float scale = rsqrtf(sh[0] * (1.f / 16384.f) + 1.1920929e-07f);
    float* op = out + (size_t)n * 16384;
    for (int i = threadIdx.x; i < 16384; i += 256) op[i] = xp[i] * scale * w[i];
}

// ---------------------------------------------------------------------------
// Embedding row norms
// ---------------------------------------------------------------------------
__global__ void enorm_kernel(const float* __restrict__ e, float* __restrict__ en) {
    int j = blockIdx.x * 256 + threadIdx.x;
    if (j >= NE) return;
    const float* r = e + (size_t)j * HS;
    float s = 0.f;
    for (int c = 0; c < HS; c++) { float v = r[c]; s += v * v; }
    en[j] = s;
}

// ---------------------------------------------------------------------------
// VQ argmin (first-min tiebreak, matching jnp.argmin) + gather q (NCHW)
// scores layout: [n][class][hw]
// ---------------------------------------------------------------------------
__global__ __launch_bounds__(256) void vq_argmin_kernel(const float* __restrict__ scores,
                                                        const float* __restrict__ en,
                                                        const float* __restrict__ emb,
                                                        float* __restrict__ q) {
    int token = blockIdx.x * 8 + (threadIdx.x >> 5);
    int lane = threadIdx.x & 31;
    int n = token >> 6, hw = token & 63;
    const float* sc = scores + ((size_t)n * NE) * 64 + hw;
    float best = 3.4e38f;
    int bj = NE;
    for (int j = lane; j < NE; j += 32) {
        float d = en[j] - 2.f * sc[(size_t)j * 64];
        if (d < best || (d == best && j < bj)) { best = d; bj = j; }
    }
#pragma unroll
    for (int off = 16; off; off >>= 1) {
        float ob = __shfl_down_sync(0xffffffffu, best, off);
        int oj = __shfl_down_sync(0xffffffffu, bj, off);
        if (ob < best || (ob == best && oj < bj)) { best = ob; bj = oj; }
    }
    bj = __shfl_sync(0xffffffffu, bj, 0);
    const float* er = emb + (size_t)bj * HS;
    float* qp = q + (size_t)n * HS * 64 + hw;
    for (int c = lane; c < HS; c += 32) qp[(size_t)c * 64] = er[c];
}

// ---------------------------------------------------------------------------
// Squared-diff partial reduction (deterministic two-stage)
// ---------------------------------------------------------------------------
__global__ __launch_bounds__(256) void sqdiff_kernel(const float* __restrict__ a,
                                                     const float* __restrict__ b,
                                                     float* __restrict__ part, int nelem) {
    float s = 0.f;
    for (int i = blockIdx.x * 256 + threadIdx.x; i < nelem; i += 256 * 256) {
        float d = a[i] - b[i];
        s += d * d;
    }
    __shared__ float sh[256];
    sh[threadIdx.x] = s;
    __syncthreads();
    for (int st = 128; st > 0; st >>= 1) {
        if (threadIdx.x < st) sh[threadIdx.x] += sh[threadIdx.x + st];
        __syncthreads();
    }
    if (threadIdx.x == 0) part[blockIdx.x] = sh[0];
}

__global__ void finalize_kernel(const float* __restrict__ partVq,
                                const float* __restrict__ partRec,
                                float* __restrict__ out) {
    if (threadIdx.x == 0 && blockIdx.x == 0) {
        float svq = 0.f, sre = 0.f;
        for (int i = 0; i < 256; i++) { svq += partVq[i]; sre += partRec[i]; }
        float dict = svq * (1.f / 4194304.f);   // mean over 256*256*64
        float rec = sre * (1.f / 786432.f);     // mean over 256*3*32*32
        out[0] = rec + dict + dict;             // total (beta=1, commit==dict)
        out[1] = rec;
        out[2] = dict;
        out[3] = dict;
    }
}

// ---------------------------------------------------------------------------
// Deconv1 parity weight prep:
//   wp[((p*256 + oc)*256 + ic)*4 + a*2 + b] = w1[ic][oc][3-(ph+2a)][3-(pw+2b)]
// ---------------------------------------------------------------------------
__global__ void prep_wp_kernel(const float* __restrict__ w, float* __restrict__ wp) {
    int idx = blockIdx.x * 256 + threadIdx.x;
    if (idx >= 1048576) return;
    int b = idx & 1;
    int a = (idx >> 1) & 1;
    int ic = (idx >> 2) & 255;
    int oc = (idx >> 10) & 255;
    int p = idx >> 18;
    int ph = p >> 1, pw = p & 1;
    int kh = ph + 2 * a, kw = pw + 2 * b;
    wp[idx] = w[((size_t)(ic * 256 + oc) * 4 + (3 - kh)) * 4 + (3 - kw)];
}

// ---------------------------------------------------------------------------
// Deconv2 (256->3 ch, 16x16 -> 32x32, k4 s2 p1), direct per-parity kernel.
// Block = (n, parity); each thread computes one output pixel, all 3 oc.
// ---------------------------------------------------------------------------
__global__ __launch_bounds__(256) void deconv2_kernel(const float* __restrict__ in,
                                                      const float* __restrict__ w,
                                                      const float* __restrict__ bias,
                                                      float* __restrict__ out) {
    __shared__ float wsh[4 * 256 * 3];  // [tap][ic][oc]
    const int n = blockIdx.x;
    const int par = blockIdx.y;
    const int ph = par >> 1, pw = par & 1;
    const int tid = threadIdx.x;

    for (int idx = tid; idx < 3072; idx += 256) {
        int oc = idx % 3;
        int rest = idx / 3;
        int ic = rest & 255;
        int t = rest >> 8;
        int a = t >> 1, b = t & 1;
        int kh = ph + 2 * a, kw = pw + 2 * b;
        wsh[idx] = w[((size_t)(ic * 3 + oc) * 4 + (3 - kh)) * 4 + (3 - kw)];
    }
    __syncthreads();

    const int i = tid >> 4, j = tid & 15;
    const int oh = 2 * i + ph, ow = 2 * j + pw;
    float acc0 = 0.f, acc1 = 0.f, acc2 = 0.f;

    int base[4];
    bool ok[4];
#pragma unroll
    for (int t = 0; t < 4; t++) {
        int a = t >> 1, b = t & 1;
        int ih = i + ph + a - 1, iw = j + pw + b - 1;
        ok[t] = ((unsigned)ih < 16u) && ((unsigned)iw < 16u);
        base[t] = ok[t] ? (n * 65536 + ih * 16 + iw) : 0;
    }
    for (int ic = 0; ic < 256; ic++) {
        int ico = ic * 256;
#pragma unroll
        for (int t = 0; t < 4; t++) {
            if (ok[t]) {
                float v = in[base[t] + ico];
                const float* wp2 = &wsh[(t * 256 + ic) * 3];
                acc0 += v * wp2[0];
                acc1 += v * wp2[1];
                acc2 += v * wp2[2];
            }
        }
    }
    size_t o = (size_t)n * 3072 + (size_t)oh * 32 + ow;
    out[o] = acc0 + bias[0];
    out[o + 1024] = acc1 + bias[1];
    out[o + 2048] = acc2 + bias[2];
}

// ---------------------------------------------------------------------------
// Host helpers
// ---------------------------------------------------------------------------
static void launch_gemm(const float* A, const float* W, const float* bias, const float* res,
                        float* out, int M, int N, int K,
                        int IC, int KH, int KW, int IH, int IW, int OH, int OW,
                        int stride, int padh, int padw,
                        int oscale, int ooffh, int ooffw, int oW, int oHW, int mode) {
    GemmP p;
    p.A = A; p.W = W; p.bias = bias; p.res = res; p.out = out;
    p.M = M; p.N = N; p.K = K;
    p.IC = IC; p.KH = KH; p.KW = KW; p.IH = IH; p.IW = IW; p.OH = OH; p.OW = OW;
    p.stride = stride; p.padh = padh; p.padw = padw;
    p.oscale = oscale; p.ooffh = ooffh; p.ooffw = ooffw; p.oW = oW; p.oHW = oHW;
    p.mode = mode;
    dim3 g(M / 64, N / 64);
    conv_gemm<<<g, 256>>>(p);
}

static void res_block(float* xb, float* tb, const float* rmsw,
                      const float* w3, const float* b3,
                      const float* w1, const float* b1) {
    rmsnorm_kernel<<<256, 256>>>(xb, rmsw, tb);
    launch_gemm(tb, w3, b3, xb, xb, 16384, 256, 2304,
                256, 3, 3, 8, 8, 8, 8, 1, 1, 1,
                1, 0, 0, 8, 64, 2);
    rmsnorm_kernel<<<256, 256>>>(xb, rmsw + 16384, tb);
    launch_gemm(tb, w1, b1, xb, xb, 16384, 256, 256,
                256, 1, 1, 8, 8, 8, 8, 1, 0, 0,
                1, 0, 0, 8, 64, 2);
}

extern "C" void kernel_launch(void* const* d_in, const int* in_sizes, int n_in,
                              void* d_out, int out_size) {
    const float* x       = (const float*)d_in[0];
    const float* enc_w1  = (const float*)d_in[1];
    const float* enc_b1  = (const float*)d_in[2];
    const float* enc_w2  = (const float*)d_in[3];
    const float* enc_b2  = (const float*)d_in[4];
    const float* rms_w   = (const float*)d_in[5];   // (4,2,256,8,8)
    const float* c3_w    = (const float*)d_in[6];   // (4,256,256,3,3)
    const float* c3_b    = (const float*)d_in[7];   // (4,256)
    const float* c1_w    = (const float*)d_in[8];   // (4,256,256,1,1)
    const float* c1_b    = (const float*)d_in[9];   // (4,256)
    const float* emb     = (const float*)d_in[10];  // (512,256)
    const float* dec_w1  = (const float*)d_in[11];  // (256,256,4,4) in,out
    const float* dec_b1  = (const float*)d_in[12];
    const float* dec_w2  = (const float*)d_in[13];  // (256,3,4,4) in,out
    const float* dec_b2  = (const float*)d_in[14];
    float* out = (float*)d_out;

    float *h16, *h8, *t8, *q, *scores, *wp, *en, *part;
    cudaGetSymbolAddress((void**)&h16, g_h16);
    cudaGetSymbolAddress((void**)&h8, g_h8);
    cudaGetSymbolAddress((void**)&t8, g_t8);
    cudaGetSymbolAddress((void**)&q, g_q);
    cudaGetSymbolAddress((void**)&scores, g_scores);
    cudaGetSymbolAddress((void**)&wp, g_wp);
    cudaGetSymbolAddress((void**)&en, g_enorm);
    cudaGetSymbolAddress((void**)&part, g_part);

    // ---- Encoder ----
    // conv1: 3->256, 32x32 -> 16x16, k4 s2 p1, relu
    launch_gemm(x, enc_w1, enc_b1, nullptr, h16, 65536, 256, 48,
                3, 4, 4, 32, 32, 16, 16, 2, 1, 1,
                1, 0, 0, 16, 256, 1);
    // conv2: 256->256, 16x16 -> 8x8, k4 s2 p1, relu
    launch_gemm(h16, enc_w2, enc_b2, nullptr, h8, 16384, 256, 4096,
                256, 4, 4, 16, 16, 8, 8, 2, 1, 1,
                1, 0, 0, 8, 64, 1);
    // res blocks 0,1
    res_block(h8, t8, rms_w + 0 * 32768, c3_w + 0 * 589824, c3_b + 0 * 256,
              c1_w + 0 * 65536, c1_b + 0 * 256);
    res_block(h8, t8, rms_w + 1 * 32768, c3_w + 1 * 589824, c3_b + 1 * 256,
              c1_w + 1 * 65536, c1_b + 1 * 256);

    // ---- VQ ----
    enorm_kernel<<<2, 256>>>(emb, en);
    // scores[n][class][hw] = z . e_class  (1x1-conv gather)
    launch_gemm(h8, emb, nullptr, nullptr, scores, 16384, 512, 256,
                256, 1, 1, 8, 8, 8, 8, 1, 0, 0,
                1, 0, 0, 8, 64, 0);
    vq_argmin_kernel<<<2048, 256>>>(scores, en, emb, q);
    // vq loss (enc vs q) — must run before decoder overwrites q
    sqdiff_kernel<<<256, 256>>>(h8, q, part, 4194304);

    // ---- Decoder ----
    res_block(q, t8, rms_w + 2 * 32768, c3_w + 2 * 589824, c3_b + 2 * 256,
              c1_w + 2 * 65536, c1_b + 2 * 256);
    res_block(q, t8, rms_w + 3 * 32768, c3_w + 3 * 589824, c3_b + 3 * 256,
              c1_w + 3 * 65536, c1_b + 3 * 256);

    // deconv1: 256->256, 8x8 -> 16x16, k4 s2 p1, relu — 4 parity GEMMs
    prep_wp_kernel<<<4096, 256>>>(dec_w1, wp);
    for (int p = 0; p < 4; p++) {
        int ph = p >> 1, pw = p & 1;
        launch_gemm(q, wp + (size_t)p * 262144, dec_b1, nullptr, h16,
                    16384, 256, 1024,
                    256, 2, 2, 8, 8, 8, 8, 1, 1 - ph, 1 - pw,
                    2, ph, pw, 16, 256, 1);
    }

    // deconv2: 256->3, 16x16 -> 32x32, k4 s2 p1 (no relu) -> decoded
    deconv2_kernel<<<dim3(256, 4), 256>>>(h16, dec_w2, dec_b2, out + 4);

    // reconst loss + finalize scalars
    sqdiff_kernel<<<256, 256>>>(out + 4, x, part + 256, 786432);
    finalize_kernel<<<1, 32>>>(part, part + 256, out);
}

// round 2
// speedup vs baseline: 1.0917x; 1.0917x over previous
#include <cuda_runtime.h>
#include <cstddef>

// ---------------------------------------------------------------------------
// VQ-VAE forward, fp32. Heavy ops via one templated im2col-gather GEMM:
// 128x128 CTA tile, 8x8 per-thread, BK=16, double-buffered smem, float4 LDS.
// RMSNorm fused into the GEMM A-gather (per-sample scale precomputed).
// Scratch in __device__ globals. Graph-capturable (launches only).
// ---------------------------------------------------------------------------

#define HS 256
#define NE 512

// ---- scratch ----
__device__ __align__(16) float g_h16[16777216];   // 256*256*16*16
__device__ __align__(16) float g_h8[4194304];     // 256*256*8*8 (x buffer)
__device__ __align__(16) float g_t8[4194304];     // tmp buffer
__device__ __align__(16) float g_q[4194304];      // quantized / decoder x
__device__ __align__(16) float g_scores[8388608]; // 256*512*64
__device__ __align__(16) float g_wp[1048576];     // deconv1 parity weights
__device__ __align__(16) float g_enorm[512];
__device__ __align__(16) float g_scale[256];      // rms per-sample scale
__device__ __align__(16) float g_part[512];

struct GemmP {
    const float* A; const float* W; const float* bias; const float* res; float* out;
    const float* ascale; const float* aweight;   // fused rmsnorm (may be null)
    int N, K;
    int IC, IH, IW, OH, OW, stride, padh, padw;
    int oscale, ooffh, ooffw, oW, oHW;
    int mode;                                     // 0 plain, 1 bias+relu, 2 res+bias+relu
};

// ---------------------------------------------------------------------------
// C[m, oc] = sum_k gather(A)[m,k] * W[oc,k]; m=(n,oh,ow), k=(ic,kh,kw).
// Requires M%128==0, N%128==0, K%16==0.
// ---------------------------------------------------------------------------
template<int KH, int KW, bool RMS>
__global__ __launch_bounds__(256) void conv_gemm(GemmP p) {
    constexpr int KHKW = KH * KW;
    __shared__ float As[2][16][128];
    __shared__ float Bs[2][16][128];
    __shared__ int sBase[128], sY[128], sX[128], sN[128];

    const int tid = threadIdx.x;
    const int bm = blockIdx.x * 128;
    const int bn = blockIdx.y * 128;

    if (tid < 128) {
        int m = bm + tid;
        int ohw = p.OH * p.OW;
        int n = m / ohw;
        int rem = m - n * ohw;
        int oh = rem / p.OW;
        int ow = rem - oh * p.OW;
        sBase[tid] = n * p.IC * p.IH * p.IW;
        sY[tid] = oh * p.stride - p.padh;
        sX[tid] = ow * p.stride - p.padw;
        sN[tid] = n;
    }
    __syncthreads();

    const int IH = p.IH, IW = p.IW;
    // A-gather role: one smem row per thread, 8 consecutive k (warp-uniform jset)
    const int r = tid & 127;
    const int jset = (tid >> 7) * 8;
    const int rby = sY[r], rbx = sX[r], rbb = sBase[r];
    const float ascl = RMS ? p.ascale[sN[r]] : 1.f;
    // B-load role
    const int nb = tid & 127;
    const int kq = (tid >> 7) * 8;
    const float* Wrow = p.W + (size_t)(bn + nb) * p.K;

    float av[8];
    float4 bv0, bv1;

    auto loadAB = [&](int k0) {
#pragma unroll
        for (int q = 0; q < 8; q++) {
            int k = k0 + jset + q;
            int ic = k / KHKW;
            int kk2 = k - ic * KHKW;
            int kh = kk2 / KW;
            int kw = kk2 - kh * KW;
            int ih = rby + kh, iw = rbx + kw;
            float v = 0.f;
            if ((unsigned)ih < (unsigned)IH && (unsigned)iw < (unsigned)IW) {
                int ii = (ic * IH + ih) * IW + iw;
                v = p.A[rbb + ii];
                if (RMS) v *= ascl * p.aweight[ii];
            }
            av[q] = v;
        }
        bv0 = *(const float4*)(Wrow + k0 + kq);
        bv1 = *(const float4*)(Wrow + k0 + kq + 4);
    };
    auto storeAB = [&](int buf) {
#pragma unroll
        for (int q = 0; q < 8; q++) As[buf][jset + q][r] = av[q];
        Bs[buf][kq + 0][nb] = bv0.x; Bs[buf][kq + 1][nb] = bv0.y;
        Bs[buf][kq + 2][nb] = bv0.z; Bs[buf][kq + 3][nb] = bv0.w;
        Bs[buf][kq + 4][nb] = bv1.x; Bs[buf][kq + 5][nb] = bv1.y;
        Bs[buf][kq + 6][nb] = bv1.z; Bs[buf][kq + 7][nb] = bv1.w;
    };

    const int tr = tid >> 4;      // 0..15 -> rows tr*8..+7
    const int tc = tid & 15;      // 0..15 -> cols tc*8..+7
    float acc[8][8];
#pragma unroll
    for (int i = 0; i < 8; i++)
#pragma unroll
        for (int j = 0; j < 8; j++) acc[i][j] = 0.f;

    const int nt = p.K >> 4;
    loadAB(0);
    storeAB(0);
    __syncthreads();

    for (int t = 0; t < nt; t++) {
        const int cur = t & 1;
        if (t + 1 < nt) loadAB((t + 1) << 4);
#pragma unroll
        for (int kk = 0; kk < 16; kk++) {
            float4 a0 = *(const float4*)&As[cur][kk][tr * 8];
            float4 a1 = *(const float4*)&As[cur][kk][tr * 8 + 4];
            float4 b0 = *(const float4*)&Bs[cur][kk][tc * 8];
            float4 b1 = *(const float4*)&Bs[cur][kk][tc * 8 + 4];
            float a[8] = {a0.x, a0.y, a0.z, a0.w, a1.x, a1.y, a1.z, a1.w};
            float b[8] = {b0.x, b0.y, b0.z, b0.w, b1.x, b1.y, b1.z, b1.w};
#pragma unroll
            for (int i = 0; i < 8; i++)
#pragma unroll
                for (int j = 0; j < 8; j++) acc[i][j] += a[i] * b[j];
        }
        if (t + 1 < nt) {
            storeAB(cur ^ 1);
            __syncthreads();
        }
    }

    // epilogue
    const int ohw = p.OH * p.OW;
#pragma unroll
    for (int i = 0; i < 8; i++) {
        int m = bm + tr * 8 + i;
        int n = m / ohw;
        int rem = m - n * ohw;
        int oh = rem / p.OW;
        int ow = rem - oh * p.OW;
        int oy = oh * p.oscale + p.ooffh;
        int ox = ow * p.oscale + p.ooffw;
        size_t obase = (size_t)n * p.N * p.oHW + (size_t)oy * p.oW + ox;
#pragma unroll
        for (int j = 0; j < 8; j++) {
            int oc = bn + tc * 8 + j;
            float v = acc[i][j];
            if (p.bias) v += p.bias[oc];
            if (p.mode >= 1) v = fmaxf(v, 0.f);
            size_t oi = obase + (size_t)oc * p.oHW;
            if (p.mode == 2) v += p.res[oi];
            p.out[oi] = v;
        }
    }
}

// ---------------------------------------------------------------------------
// Per-sample RMS scale: scale[n] = rsqrt(mean(x^2)+eps) over 16384 elements
// ---------------------------------------------------------------------------
__global__ __launch_bounds__(256) void rms_scale_kernel(const float* __restrict__ in,
                                                        float* __restrict__ scale) {
    const int n = blockIdx.x;
    const float4* xp = (const float4*)(in + (size_t)n * 16384);
    float s = 0.f;
    for (int i = threadIdx.x; i < 4096; i += 256) {
        float4 v = xp[i];
        s += v.x * v.x + v.y * v.y + v.z * v.z + v.w * v.w;
    }
    __shared__ float sh[256];
    sh[threadIdx.x] = s;
    __syncthreads();
    for (int st = 128; st > 0; st >>= 1) {
        if (threadIdx.x < st) sh[threadIdx.x] += sh[threadIdx.x + st];
        __syncthreads();
    }
    if (threadIdx.x == 0)
        scale[n] = rsqrtf(sh[0] * (1.f / 16384.f) + 1.1920929e-07f);
}

__global__ void enorm_kernel(const float* __restrict__ e, float* __restrict__ en) {
    int j = blockIdx.x * 256 + threadIdx.x;
    if (j >= NE) return;
    const float* r = e + (size_t)j * HS;
    float s = 0.f;
    for (int c = 0; c < HS; c++) { float v = r[c]; s += v * v; }
    en[j] = s;
}

// VQ argmin (first-min tiebreak) + gather q (NCHW). scores: [n][class][hw]
__global__ __launch_bounds__(256) void vq_argmin_kernel(const float* __restrict__ scores,
                                                        const float* __restrict__ en,
                                                        const float* __restrict__ emb,
                                                        float* __restrict__ q) {
    int token = blockIdx.x * 8 + (threadIdx.x >> 5);
    int lane = threadIdx.x & 31;
    int n = token >> 6, hw = token & 63;
    const float* sc = scores + ((size_t)n * NE) * 64 + hw;
    float best = 3.4e38f;
    int bj = NE;
    for (int j = lane; j < NE; j += 32) {
        float d = en[j] - 2.f * sc[(size_t)j * 64];
        if (d < best || (d == best && j < bj)) { best = d; bj = j; }
    }
#pragma unroll
    for (int off = 16; off; off >>= 1) {
        float ob = __shfl_down_sync(0xffffffffu, best, off);
        int oj = __shfl_down_sync(0xffffffffu, bj, off);
        if (ob < best || (ob == best && oj < bj)) { best = ob; bj = oj; }
    }
    bj = __shfl_sync(0xffffffffu, bj, 0);
    const float* er = emb + (size_t)bj * HS;
    float* qp = q + (size_t)n * HS * 64 + hw;
    for (int c = lane; c < HS; c += 32) qp[(size_t)c * 64] = er[c];
}

__global__ __launch_bounds__(256) void sqdiff_kernel(const float* __restrict__ a,
                                                     const float* __restrict__ b,
                                                     float* __restrict__ part, int nvec4) {
    const float4* a4 = (const float4*)a;
    const float4* b4 = (const float4*)b;
    float s = 0.f;
    for (int i = blockIdx.x * 256 + threadIdx.x; i < nvec4; i += 256 * 256) {
        float4 va = a4[i], vb = b4[i];
        float dx = va.x - vb.x, dy = va.y - vb.y, dz = va.z - vb.z, dw = va.w - vb.w;
        s += dx * dx + dy * dy + dz * dz + dw * dw;
    }
    __shared__ float sh[256];
    sh[threadIdx.x] = s;
    __syncthreads();
    for (int st = 128; st > 0; st >>= 1) {
        if (threadIdx.x < st) sh[threadIdx.x] += sh[threadIdx.x + st];
        __syncthreads();
    }
    if (threadIdx.x == 0) part[blockIdx.x] = sh[0];
}

__global__ void finalize_kernel(const float* __restrict__ partVq,
                                const float* __restrict__ partRec,
                                float* __restrict__ out) {
    if (threadIdx.x == 0 && blockIdx.x == 0) {
        float svq = 0.f, sre = 0.f;
        for (int i = 0; i < 256; i++) { svq += partVq[i]; sre += partRec[i]; }
        float dict = svq * (1.f / 4194304.f);
        float rec = sre * (1.f / 786432.f);
        out[0] = rec + dict + dict;
        out[1] = rec;
        out[2] = dict;
        out[3] = dict;
    }
}

// Deconv1 parity weights: wp[((p*256+oc)*256+ic)*4 + a*2+b] = w[ic][oc][3-(ph+2a)][3-(pw+2b)]
__global__ void prep_wp_kernel(const float* __restrict__ w, float* __restrict__ wp) {
    int idx = blockIdx.x * 256 + threadIdx.x;
    if (idx >= 1048576) return;
    int b = idx & 1;
    int a = (idx >> 1) & 1;
    int ic = (idx >> 2) & 255;
    int oc = (idx >> 10) & 255;
    int p = idx >> 18;
    int ph = p >> 1, pw = p & 1;
    int kh = ph + 2 * a, kw = pw + 2 * b;
    wp[idx] = w[((size_t)(ic * 256 + oc) * 4 + (3 - kh)) * 4 + (3 - kw)];
}

// Deconv2: 256->3 ch, 16x16 -> 32x32, k4 s2 p1, per-parity direct
__global__ __launch_bounds__(256) void deconv2_kernel(const float* __restrict__ in,
                                                      const float* __restrict__ w,
                                                      const float* __restrict__ bias,
                                                      float* __restrict__ out) {
    __shared__ float wsh[4 * 256 * 3];
    const int n = blockIdx.x;
    const int par = blockIdx.y;
    const int ph = par >> 1, pw = par & 1;
    const int tid = threadIdx.x;

    for (int idx = tid; idx < 3072; idx += 256) {
        int oc = idx % 3;
        int rest = idx / 3;
        int ic = rest & 255;
        int t = rest >> 8;
        int a = t >> 1, b = t & 1;
        int kh = ph + 2 * a, kw = pw + 2 * b;
        wsh[idx] = w[((size_t)(ic * 3 + oc) * 4 + (3 - kh)) * 4 + (3 - kw)];
    }
    __syncthreads();

    const int i = tid >> 4, j = tid & 15;
    const int oh = 2 * i + ph, ow = 2 * j + pw;
    float acc0 = 0.f, acc1 = 0.f, acc2 = 0.f;

    int base[4];
    bool ok[4];
#pragma unroll
    for (int t = 0; t < 4; t++) {
        int a = t >> 1, b = t & 1;
        int ih = i + ph + a - 1, iw = j + pw + b - 1;
        ok[t] = ((unsigned)ih < 16u) && ((unsigned)iw < 16u);
        base[t] = ok[t] ? (n * 65536 + ih * 16 + iw) : 0;
    }
    for (int ic = 0; ic < 256; ic++) {
        int ico = ic * 256;
#pragma unroll
        for (int t = 0; t < 4; t++) {
            if (ok[t]) {
                float v = in[base[t] + ico];
                const float* wp2 = &wsh[(t * 256 + ic) * 3];
                acc0 += v * wp2[0];
                acc1 += v * wp2[1];
                acc2 += v * wp2[2];
            }
        }
    }
    size_t o = (size_t)n * 3072 + (size_t)oh * 32 + ow;
    out[o] = acc0 + bias[0];
    out[o + 1024] = acc1 + bias[1];
    out[o + 2048] = acc2 + bias[2];
}

// ---------------------------------------------------------------------------
// Host side
// ---------------------------------------------------------------------------
static GemmP mkP(const float* A, const float* W, const float* bias, const float* res,
                 float* out, const float* ascale, const float* aweight,
                 int N, int K, int IC, int IH, int IW, int OH, int OW,
                 int stride, int padh, int padw,
                 int oscale, int ooffh, int ooffw, int oW, int oHW, int mode) {
    GemmP p;
    p.A = A; p.W = W; p.bias = bias; p.res = res; p.out = out;
    p.ascale = ascale; p.aweight = aweight;
    p.N = N; p.K = K; p.IC = IC; p.IH = IH; p.IW = IW; p.OH = OH; p.OW = OW;
    p.stride = stride; p.padh = padh; p.padw = padw;
    p.oscale = oscale; p.ooffh = ooffh; p.ooffw = ooffw; p.oW = oW; p.oHW = oHW;
    p.mode = mode;
    return p;
}

// res block on buffer x (ends with result in x), tmp as scratch
static void res_block(float* x, float* tmp, float* scl, const float* rmsw,
                      const float* w3, const float* b3,
                      const float* w1, const float* b1) {
    rms_scale_kernel<<<256, 256>>>(x, scl);
    {   // conv3x3 with fused rmsnorm, out = x + relu(conv(rms(x)))
        GemmP p = mkP(x, w3, b3, x, tmp, scl, rmsw,
                      256, 2304, 256, 8, 8, 8, 8, 1, 1, 1,
                      1, 0, 0, 8, 64, 2);
        conv_gemm<3, 3, true><<<dim3(128, 2), 256>>>(p);
    }
    rms_scale_kernel<<<256, 256>>>(tmp, scl);
    {   // conv1x1 with fused rmsnorm, out = tmp + relu(conv(rms(tmp))) -> back to x
        GemmP p = mkP(tmp, w1, b1, tmp, x, scl, rmsw + 16384,
                      256, 256, 256, 8, 8, 8, 8, 1, 0, 0,
                      1, 0, 0, 8, 64, 2);
        conv_gemm<1, 1, true><<<dim3(128, 2), 256>>>(p);
    }
}

extern "C" void kernel_launch(void* const* d_in, const int* in_sizes, int n_in,
                              void* d_out, int out_size) {
    const float* x       = (const float*)d_in[0];
    const float* enc_w1  = (const float*)d_in[1];
    const float* enc_b1  = (const float*)d_in[2];
    const float* enc_w2  = (const float*)d_in[3];
    const float* enc_b2  = (const float*)d_in[4];
    const float* rms_w   = (const float*)d_in[5];
    const float* c3_w    = (const float*)d_in[6];
    const float* c3_b    = (const float*)d_in[7];
    const float* c1_w    = (const float*)d_in[8];
    const float* c1_b    = (const float*)d_in[9];
    const float* emb     = (const float*)d_in[10];
    const float* dec_w1  = (const float*)d_in[11];
    const float* dec_b1  = (const float*)d_in[12];
    const float* dec_w2  = (const float*)d_in[13];
    const float* dec_b2  = (const float*)d_in[14];
    float* out = (float*)d_out;

    float *h16, *h8, *t8, *q, *scores, *wp, *en, *scl, *part;
    cudaGetSymbolAddress((void**)&h16, g_h16);
    cudaGetSymbolAddress((void**)&h8, g_h8);
    cudaGetSymbolAddress((void**)&t8, g_t8);
    cudaGetSymbolAddress((void**)&q, g_q);
    cudaGetSymbolAddress((void**)&scores, g_scores);
    cudaGetSymbolAddress((void**)&wp, g_wp);
    cudaGetSymbolAddress((void**)&en, g_enorm);
    cudaGetSymbolAddress((void**)&scl, g_scale);
    cudaGetSymbolAddress((void**)&part, g_part);

    // ---- Encoder ----
    {   // conv1: 3->256, 32x32->16x16, k4 s2 p1, relu
        GemmP p = mkP(x, enc_w1, enc_b1, nullptr, h16, nullptr, nullptr,
                      256, 48, 3, 32, 32, 16, 16, 2, 1, 1,
                      1, 0, 0, 16, 256, 1);
        conv_gemm<4, 4, false><<<dim3(512, 2), 256>>>(p);
    }
    {   // conv2: 256->256, 16x16->8x8, k4 s2 p1, relu
        GemmP p = mkP(h16, enc_w2, enc_b2, nullptr, h8, nullptr, nullptr,
                      256, 4096, 256, 16, 16, 8, 8, 2, 1, 1,
                      1, 0, 0, 8, 64, 1);
        conv_gemm<4, 4, false><<<dim3(128, 2), 256>>>(p);
    }
    res_block(h8, t8, scl, rms_w + 0 * 32768, c3_w + 0 * 589824, c3_b + 0 * 256,
              c1_w + 0 * 65536, c1_b + 0 * 256);
    res_block(h8, t8, scl, rms_w + 1 * 32768, c3_w + 1 * 589824, c3_b + 1 * 256,
              c1_w + 1 * 65536, c1_b + 1 * 256);

    // ---- VQ ----
    enorm_kernel<<<2, 256>>>(emb, en);
    {   // scores[n][class][hw] = z . e_class
        GemmP p = mkP(h8, emb, nullptr, nullptr, scores, nullptr, nullptr,
                      512, 256, 256, 8, 8, 8, 8, 1, 0, 0,
                      1, 0, 0, 8, 64, 0);
        conv_gemm<1, 1, false><<<dim3(128, 4), 256>>>(p);
    }
    vq_argmin_kernel<<<2048, 256>>>(scores, en, emb, q);
    sqdiff_kernel<<<256, 256>>>(h8, q, part, 1048576);

    // ---- Decoder ----
    res_block(q, t8, scl, rms_w + 2 * 32768, c3_w + 2 * 589824, c3_b + 2 * 256,
              c1_w + 2 * 65536, c1_b + 2 * 256);
    res_block(q, t8, scl, rms_w + 3 * 32768, c3_w + 3 * 589824, c3_b + 3 * 256,
              c1_w + 3 * 65536, c1_b + 3 * 256);

    // deconv1: 4 parity GEMMs, 8x8 -> 16x16
    prep_wp_kernel<<<4096, 256>>>(dec_w1, wp);
    for (int par = 0; par < 4; par++) {
        int ph = par >> 1, pw = par & 1;
        GemmP p = mkP(q, wp + (size_t)par * 262144, dec_b1, nullptr, h16, nullptr, nullptr,
                      256, 1024, 256, 8, 8, 8, 8, 1, 1 - ph, 1 - pw,
                      2, ph, pw, 16, 256, 1);
        conv_gemm<2, 2, false><<<dim3(128, 2), 256>>>(p);
    }

    // deconv2: 256->3, 16x16->32x32 -> decoded
    deconv2_kernel<<<dim3(256, 4), 256>>>(h16, dec_w2, dec_b2, out + 4);

    // losses
    sqdiff_kernel<<<256, 256>>>(out + 4, x, part + 256, 196608);
    finalize_kernel<<<1, 32>>>(part, part + 256, out);
}

// round 4
// speedup vs baseline: 1.4404x; 1.3195x over previous
#include <cuda_runtime.h>
#include <cstddef>

// ---------------------------------------------------------------------------
// VQ-VAE forward. Convs on the tensor pipe via 3xTF32 mma.sync.m16n8k8
// (fp32-class accuracy: a=ah+al, b=bh+bl, acc += ah*bh + ah*bl + al*bh).
// VQ scores GEMM exact fp32 SIMT. Scratch in __device__ globals.
// ---------------------------------------------------------------------------

#define HS 256
#define NE 512

__device__ __align__(16) float g_h16[16777216];
__device__ __align__(16) float g_h8[4194304];
__device__ __align__(16) float g_t8[4194304];
__device__ __align__(16) float g_q[4194304];
__device__ __align__(16) float g_scores[8388608];
__device__ __align__(16) float g_wp[1048576];
__device__ __align__(16) float g_enorm[512];
__device__ __align__(16) float g_scale[256];
__device__ __align__(16) float g_part[512];

struct GemmP {
    const float* A; const float* W; const float* bias; const float* res; float* out;
    const float* ascale; const float* aweight;
    int N, K;
    int IC, IH, IW, OH, OW, stride, padh, padw;
    int oscale, ooffh, ooffw, oW, oHW;
    int mode;   // 0 plain, 1 bias+relu, 2 res+bias+relu
};

__device__ __forceinline__ unsigned f2tf32(float v) {
    unsigned u;
    asm("cvt.rna.tf32.f32 %0, %1;" : "=r"(u) : "f"(v));
    return u;
}

__device__ __forceinline__ void mma_tf32(float* d, const unsigned* a, const unsigned* b) {
    asm volatile(
        "mma.sync.aligned.m16n8k8.row.col.f32.tf32.tf32.f32 "
        "{%0,%1,%2,%3}, {%4,%5,%6,%7}, {%8,%9}, {%0,%1,%2,%3};"
        : "+f"(d[0]), "+f"(d[1]), "+f"(d[2]), "+f"(d[3])
        : "r"(a[0]), "r"(a[1]), "r"(a[2]), "r"(a[3]), "r"(b[0]), "r"(b[1]));
}

// ---------------------------------------------------------------------------
// 3xTF32 tensor-core conv GEMM: 128x128 CTA, K-tile 16, warps 2(m)x4(n).
// ---------------------------------------------------------------------------
template<int KH, int KW, bool RMS>
__global__ __launch_bounds__(256) void conv_tc(GemmP p) {
    constexpr int KHKW = KH * KW;
    __shared__ unsigned Ah[16 * 136], Al[16 * 136];
    __shared__ unsigned Bh[16 * 136], Bl[16 * 136];
    __shared__ int sY[128], sX[128], sBase[128], sObase[128];
    __shared__ float sScl[128];

    const int tid = threadIdx.x;
    const int bm = blockIdx.x * 128;
    const int bn = blockIdx.y * 128;

    if (tid < 128) {
        int m = bm + tid;
        int ohw = p.OH * p.OW;
        int n = m / ohw;
        int rem = m - n * ohw;
        int oh = rem / p.OW;
        int ow = rem - oh * p.OW;
        sBase[tid] = n * p.IC * p.IH * p.IW;
        sY[tid] = oh * p.stride - p.padh;
        sX[tid] = ow * p.stride - p.padw;
        sObase[tid] = n * p.N * p.oHW + (oh * p.oscale + p.ooffh) * p.oW
                      + (ow * p.oscale + p.ooffw);
        sScl[tid] = RMS ? p.ascale[n] : 1.f;
    }
    __syncthreads();

    const int IH = p.IH, IW = p.IW;
    const int r = tid & 127;
    const int jset = (tid >> 7) * 8;
    const int rby = sY[r], rbx = sX[r], rbb = sBase[r];
    const float ascl = sScl[r];
    const int nb = tid & 127;
    const int kq = (tid >> 7) * 8;
    const float* Wrow = p.W + (size_t)(bn + nb) * p.K;

    const int w = tid >> 5, lane = tid & 31;
    const int wm = (w & 1) * 64, wn = (w >> 1) * 32;
    const int lg = lane >> 2, lk = lane & 3;

    float acc[4][4][4];
#pragma unroll
    for (int i = 0; i < 4; i++)
#pragma unroll
        for (int j = 0; j < 4; j++)
#pragma unroll
            for (int e = 0; e < 4; e++) acc[i][j][e] = 0.f;

    float avf[8];
    float bvf[8];

    auto gather = [&](int k0) {
#pragma unroll
        for (int q = 0; q < 8; q++) {
            int k = k0 + jset + q;
            int ic = k / KHKW;
            int kk2 = k - ic * KHKW;
            int kh = kk2 / KW;
            int kw = kk2 - kh * KW;
            int ih = rby + kh, iw = rbx + kw;
            float v = 0.f;
            if ((unsigned)ih < (unsigned)IH && (unsigned)iw < (unsigned)IW) {
                int ii = (ic * IH + ih) * IW + iw;
                v = p.A[rbb + ii];
                if (RMS) v *= ascl * p.aweight[ii];
            }
            avf[q] = v;
        }
        float4 b0 = *(const float4*)(Wrow + k0 + kq);
        float4 b1 = *(const float4*)(Wrow + k0 + kq + 4);
        bvf[0] = b0.x; bvf[1] = b0.y; bvf[2] = b0.z; bvf[3] = b0.w;
        bvf[4] = b1.x; bvf[5] = b1.y; bvf[6] = b1.z; bvf[7] = b1.w;
    };
    auto store = [&]() {
#pragma unroll
        for (int q = 0; q < 8; q++) {
            unsigned h = f2tf32(avf[q]);
            unsigned l = f2tf32(avf[q] - __uint_as_float(h));
            Ah[(jset + q) * 136 + r] = h;
            Al[(jset + q) * 136 + r] = l;
        }
#pragma unroll
        for (int q = 0; q < 8; q++) {
            unsigned h = f2tf32(bvf[q]);
            unsigned l = f2tf32(bvf[q] - __uint_as_float(h));
            Bh[(kq + q) * 136 + nb] = h;
            Bl[(kq + q) * 136 + nb] = l;
        }
    };

    const int ntiles = p.K >> 4;
    gather(0);
    for (int t = 0; t < ntiles; t++) {
        __syncthreads();
        store();
        __syncthreads();
        if (t + 1 < ntiles) gather((t + 1) << 4);
#pragma unroll
        for (int ks = 0; ks < 2; ks++) {
            const int k0 = ks * 8;
            unsigned afh[4][4], afl[4][4], bfh[4][2], bfl[4][2];
#pragma unroll
            for (int mt = 0; mt < 4; mt++) {
                int ml = wm + mt * 16 + lg;
                int i0 = (k0 + lk) * 136 + ml;
                int i1 = (k0 + lk + 4) * 136 + ml;
                afh[mt][0] = Ah[i0];     afh[mt][1] = Ah[i0 + 8];
                afh[mt][2] = Ah[i1];     afh[mt][3] = Ah[i1 + 8];
                afl[mt][0] = Al[i0];     afl[mt][1] = Al[i0 + 8];
                afl[mt][2] = Al[i1];     afl[mt][3] = Al[i1 + 8];
            }
#pragma unroll
            for (int nt = 0; nt < 4; nt++) {
                int nl = wn + nt * 8 + lg;
                int i0 = (k0 + lk) * 136 + nl;
                int i1 = (k0 + lk + 4) * 136 + nl;
                bfh[nt][0] = Bh[i0];     bfh[nt][1] = Bh[i1];
                bfl[nt][0] = Bl[i0];     bfl[nt][1] = Bl[i1];
            }
#pragma unroll
            for (int mt = 0; mt < 4; mt++)
#pragma unroll
                for (int nt = 0; nt < 4; nt++) {
                    mma_tf32(acc[mt][nt], afh[mt], bfh[nt]);
                    mma_tf32(acc[mt][nt], afl[mt], bfh[nt]);
                    mma_tf32(acc[mt][nt], afh[mt], bfl[nt]);
                }
        }
    }

    const int oHW = p.oHW;
#pragma unroll
    for (int mt = 0; mt < 4; mt++) {
#pragma unroll
        for (int half = 0; half < 2; half++) {
            int ml = wm + mt * 16 + lg + half * 8;
            int obase = sObase[ml];
#pragma unroll
            for (int nt = 0; nt < 4; nt++) {
                int oc = bn + wn + nt * 8 + lk * 2;
                float v0 = acc[mt][nt][half * 2 + 0];
                float v1 = acc[mt][nt][half * 2 + 1];
                if (p.bias) { v0 += p.bias[oc]; v1 += p.bias[oc + 1]; }
                if (p.mode >= 1) { v0 = fmaxf(v0, 0.f); v1 = fmaxf(v1, 0.f); }
                size_t oi0 = (size_t)obase + (size_t)oc * oHW;
                size_t oi1 = oi0 + oHW;
                if (p.mode == 2) { v0 += p.res[oi0]; v1 += p.res[oi1]; }
                p.out[oi0] = v0;
                p.out[oi1] = v1;
            }
        }
    }
}

// ---------------------------------------------------------------------------
// Exact fp32 SIMT GEMM (VQ scores, 1x1). 128x128 tile, 8x8/thread.
// ---------------------------------------------------------------------------
__global__ __launch_bounds__(256) void conv_gemm_simt(GemmP p) {
    __shared__ float As[2][16][128];
    __shared__ float Bs[2][16][128];
    __shared__ int sBase[128];

    const int tid = threadIdx.x;
    const int bm = blockIdx.x * 128;
    const int bn = blockIdx.y * 128;

    if (tid < 128) {
        int m = bm + tid;
        int ohw = p.OH * p.OW;
        int n = m / ohw;
        int rem = m - n * ohw;
        sBase[tid] = n * p.IC * p.IH * p.IW + rem;
    }
    __syncthreads();

    const int r = tid & 127;
    const int jset = (tid >> 7) * 8;
    const int rbb = sBase[r];
    const int nb = tid & 127;
    const int kq = (tid >> 7) * 8;
    const float* Wrow = p.W + (size_t)(bn + nb) * p.K;
    const int HWi = p.IH * p.IW;

    float av[8];
    float4 bv0, bv1;
    auto loadAB = [&](int k0) {
#pragma unroll
        for (int q = 0; q < 8; q++) {
            int ic = k0 + jset + q;
            av[q] = p.A[rbb + ic * HWi];
        }
        bv0 = *(const float4*)(Wrow + k0 + kq);
        bv1 = *(const float4*)(Wrow + k0 + kq + 4);
    };
    auto storeAB = [&](int buf) {
#pragma unroll
        for (int q = 0; q < 8; q++) As[buf][jset + q][r] = av[q];
        Bs[buf][kq + 0][nb] = bv0.x; Bs[buf][kq + 1][nb] = bv0.y;
        Bs[buf][kq + 2][nb] = bv0.z; Bs[buf][kq + 3][nb] = bv0.w;
        Bs[buf][kq + 4][nb] = bv1.x; Bs[buf][kq + 5][nb] = bv1.y;
        Bs[buf][kq + 6][nb] = bv1.z; Bs[buf][kq + 7][nb] = bv1.w;
    };

    const int tr = tid >> 4;
    const int tc = tid & 15;
    float acc[8][8];
#pragma unroll
    for (int i = 0; i < 8; i++)
#pragma unroll
        for (int j = 0; j < 8; j++) acc[i][j] = 0.f;

    const int nt = p.K >> 4;
    loadAB(0);
    storeAB(0);
    __syncthreads();
    for (int t = 0; t < nt; t++) {
        const int cur = t & 1;
        if (t + 1 < nt) loadAB((t + 1) << 4);
#pragma unroll
        for (int kk = 0; kk < 16; kk++) {
            float4 a0 = *(const float4*)&As[cur][kk][tr * 8];
            float4 a1 = *(const float4*)&As[cur][kk][tr * 8 + 4];
            float4 b0 = *(const float4*)&Bs[cur][kk][tc * 8];
            float4 b1 = *(const float4*)&Bs[cur][kk][tc * 8 + 4];
            float a[8] = {a0.x, a0.y, a0.z, a0.w, a1.x, a1.y, a1.z, a1.w};
            float b[8] = {b0.x, b0.y, b0.z, b0.w, b1.x, b1.y, b1.z, b1.w};
#pragma unroll
            for (int i = 0; i < 8; i++)
#pragma unroll
                for (int j = 0; j < 8; j++) acc[i][j] += a[i] * b[j];
        }
        if (t + 1 < nt) {
            storeAB(cur ^ 1);
            __syncthreads();
        }
    }

    const int ohw = p.OH * p.OW;
#pragma unroll
    for (int i = 0; i < 8; i++) {
        int m = bm + tr * 8 + i;
        int n = m / ohw;
        int rem = m - n * ohw;
        size_t obase = (size_t)n * p.N * p.oHW + rem;
#pragma unroll
        for (int j = 0; j < 8; j++) {
            int oc = bn + tc * 8 + j;
            p.out[obase + (size_t)oc * p.oHW] = acc[i][j];
        }
    }
}

// ---------------------------------------------------------------------------
__global__ __launch_bounds__(256) void rms_scale_kernel(const float* __restrict__ in,
                                                        float* __restrict__ scale) {
    const int n = blockIdx.x;
    const float4* xp = (const float4*)(in + (size_t)n * 16384);
    float s = 0.f;
    for (int i = threadIdx.x; i < 4096; i += 256) {
        float4 v = xp[i];
        s += v.x * v.x + v.y * v.y + v.z * v.z + v.w * v.w;
    }
    __shared__ float sh[256];
    sh[threadIdx.x] = s;
    __syncthreads();
    for (int st = 128; st > 0; st >>= 1) {
        if (threadIdx.x < st) sh[threadIdx.x] += sh[threadIdx.x + st];
        __syncthreads();
    }
    if (threadIdx.x == 0)
        scale[n] = rsqrtf(sh[0] * (1.f / 16384.f) + 1.1920929e-07f);
}

__global__ void enorm_kernel(const float* __restrict__ e, float* __restrict__ en) {
    int j = blockIdx.x * 256 + threadIdx.x;
    if (j >= NE) return;
    const float* r = e + (size_t)j * HS;
    float s = 0.f;
    for (int c = 0; c < HS; c++) { float v = r[c]; s += v * v; }
    en[j] = s;
}

__global__ __launch_bounds__(256) void vq_argmin_kernel(const float* __restrict__ scores,
                                                        const float* __restrict__ en,
                                                        const float* __restrict__ emb,
                                                        float* __restrict__ q) {
    int token = blockIdx.x * 8 + (threadIdx.x >> 5);
    int lane = threadIdx.x & 31;
    int n = token >> 6, hw = token & 63;
    const float* sc = scores + ((size_t)n * NE) * 64 + hw;
    float best = 3.4e38f;
    int bj = NE;
    for (int j = lane; j < NE; j += 32) {
        float d = en[j] - 2.f * sc[(size_t)j * 64];
        if (d < best || (d == best && j < bj)) { best = d; bj = j; }
    }
#pragma unroll
    for (int off = 16; off; off >>= 1) {
        float ob = __shfl_down_sync(0xffffffffu, best, off);
        int oj = __shfl_down_sync(0xffffffffu, bj, off);
        if (ob < best || (ob == best && oj < bj)) { best = ob; bj = oj; }
    }
    bj = __shfl_sync(0xffffffffu, bj, 0);
    const float* er = emb + (size_t)bj * HS;
    float* qp = q + (size_t)n * HS * 64 + hw;
    for (int c = lane; c < HS; c += 32) qp[(size_t)c * 64] = er[c];
}

__global__ __launch_bounds__(256) void sqdiff_kernel(const float* __restrict__ a,
                                                     const float* __restrict__ b,
                                                     float* __restrict__ part, int nvec4) {
    const float4* a4 = (const float4*)a;
    const float4* b4 = (const float4*)b;
    float s = 0.f;
    for (int i = blockIdx.x * 256 + threadIdx.x; i < nvec4; i += 256 * 256) {
        float4 va = a4[i], vb = b4[i];
        float dx = va.x - vb.x, dy = va.y - vb.y, dz = va.z - vb.z, dw = va.w - vb.w;
        s += dx * dx + dy * dy + dz * dz + dw * dw;
    }
    __shared__ float sh[256];
    sh[threadIdx.x] = s;
    __syncthreads();
    for (int st = 128; st > 0; st >>= 1) {
        if (threadIdx.x < st) sh[threadIdx.x] += sh[threadIdx.x + st];
        __syncthreads();
    }
    if (threadIdx.x == 0) part[blockIdx.x] = sh[0];
}

__global__ void finalize_kernel(const float* __restrict__ partVq,
                                const float* __restrict__ partRec,
                                float* __restrict__ out) {
    if (threadIdx.x == 0 && blockIdx.x == 0) {
        float svq = 0.f, sre = 0.f;
        for (int i = 0; i < 256; i++) { svq += partVq[i]; sre += partRec[i]; }
        float dict = svq * (1.f / 4194304.f);
        float rec = sre * (1.f / 786432.f);
        out[0] = rec + dict + dict;
        out[1] = rec;
        out[2] = dict;
        out[3] = dict;
    }
}

__global__ void prep_wp_kernel(const float* __restrict__ w, float* __restrict__ wp) {
    int idx = blockIdx.x * 256 + threadIdx.x;
    if (idx >= 1048576) return;
    int b = idx & 1;
    int a = (idx >> 1) & 1;
    int ic = (idx >> 2) & 255;
    int oc = (idx >> 10) & 255;
    int p = idx >> 18;
    int ph = p >> 1, pw = p & 1;
    int kh = ph + 2 * a, kw = pw + 2 * b;
    wp[idx] = w[((size_t)(ic * 256 + oc) * 4 + (3 - kh)) * 4 + (3 - kw)];
}

__global__ __launch_bounds__(256) void deconv2_kernel(const float* __restrict__ in,
                                                      const float* __restrict__ w,
                                                      const float* __restrict__ bias,
                                                      float* __restrict__ out) {
    __shared__ float wsh[4 * 256 * 3];
    const int n = blockIdx.x;
    const int par = blockIdx.y;
    const int ph = par >> 1, pw = par & 1;
    const int tid = threadIdx.x;

    for (int idx = tid; idx < 3072; idx += 256) {
        int oc = idx % 3;
        int rest = idx / 3;
        int ic = rest & 255;
        int t = rest >> 8;
        int a = t >> 1, b = t & 1;
        int kh = ph + 2 * a, kw = pw + 2 * b;
        wsh[idx] = w[((size_t)(ic * 3 + oc) * 4 + (3 - kh)) * 4 + (3 - kw)];
    }
    __syncthreads();

    const int i = tid >> 4, j = tid & 15;
    const int oh = 2 * i + ph, ow = 2 * j + pw;
    float acc0 = 0.f, acc1 = 0.f, acc2 = 0.f;

    int base[4];
    bool ok[4];
#pragma unroll
    for (int t = 0; t < 4; t++) {
        int a = t >> 1, b = t & 1;
        int ih = i + ph + a - 1, iw = j + pw + b - 1;
        ok[t] = ((unsigned)ih < 16u) && ((unsigned)iw < 16u);
        base[t] = ok[t] ? (n * 65536 + ih * 16 + iw) : 0;
    }
    for (int ic = 0; ic < 256; ic++) {
        int ico = ic * 256;
#pragma unroll
        for (int t = 0; t < 4; t++) {
            if (ok[t]) {
                float v = in[base[t] + ico];
                const float* wp2 = &wsh[(t * 256 + ic) * 3];
                acc0 += v * wp2[0];
                acc1 += v * wp2[1];
                acc2 += v * wp2[2];
            }
        }
    }
    size_t o = (size_t)n * 3072 + (size_t)oh * 32 + ow;
    out[o] = acc0 + bias[0];
    out[o + 1024] = acc1 + bias[1];
    out[o + 2048] = acc2 + bias[2];
}

// ---------------------------------------------------------------------------
static GemmP mkP(const float* A, const float* W, const float* bias, const float* res,
                 float* out, const float* ascale, const float* aweight,
                 int N, int K, int IC, int IH, int IW, int OH, int OW,
                 int stride, int padh, int padw,
                 int oscale, int ooffh, int ooffw, int oW, int oHW, int mode) {
    GemmP p;
    p.A = A; p.W = W; p.bias = bias; p.res = res; p.out = out;
    p.ascale = ascale; p.aweight = aweight;
    p.N = N; p.K = K; p.IC = IC; p.IH = IH; p.IW = IW; p.OH = OH; p.OW = OW;
    p.stride = stride; p.padh = padh; p.padw = padw;
    p.oscale = oscale; p.ooffh = ooffh; p.ooffw = ooffw; p.oW = oW; p.oHW = oHW;
    p.mode = mode;
    return p;
}

static void res_block(float* x, float* tmp, float* scl, const float* rmsw,
                      const float* w3, const float* b3,
                      const float* w1, const float* b1) {
    rms_scale_kernel<<<256, 256>>>(x, scl);
    {
        GemmP p = mkP(x, w3, b3, x, tmp, scl, rmsw,
                      256, 2304, 256, 8, 8, 8, 8, 1, 1, 1,
                      1, 0, 0, 8, 64, 2);
        conv_tc<3, 3, true><<<dim3(128, 2), 256>>>(p);
    }
    rms_scale_kernel<<<256, 256>>>(tmp, scl);
    {
        GemmP p = mkP(tmp, w1, b1, tmp, x, scl, rmsw + 16384,
                      256, 256, 256, 8, 8, 8, 8, 1, 0, 0,
                      1, 0, 0, 8, 64, 2);
        conv_tc<1, 1, true><<<dim3(128, 2), 256>>>(p);
    }
}

extern "C" void kernel_launch(void* const* d_in, const int* in_sizes, int n_in,
                              void* d_out, int out_size) {
    const float* x       = (const float*)d_in[0];
    const float* enc_w1  = (const float*)d_in[1];
    const float* enc_b1  = (const float*)d_in[2];
    const float* enc_w2  = (const float*)d_in[3];
    const float* enc_b2  = (const float*)d_in[4];
    const float* rms_w   = (const float*)d_in[5];
    const float* c3_w    = (const float*)d_in[6];
    const float* c3_b    = (const float*)d_in[7];
    const float* c1_w    = (const float*)d_in[8];
    const float* c1_b    = (const float*)d_in[9];
    const float* emb     = (const float*)d_in[10];
    const float* dec_w1  = (const float*)d_in[11];
    const float* dec_b1  = (const float*)d_in[12];
    const float* dec_w2  = (const float*)d_in[13];
    const float* dec_b2  = (const float*)d_in[14];
    float* out = (float*)d_out;

    float *h16, *h8, *t8, *q, *scores, *wp, *en, *scl, *part;
    cudaGetSymbolAddress((void**)&h16, g_h16);
    cudaGetSymbolAddress((void**)&h8, g_h8);
    cudaGetSymbolAddress((void**)&t8, g_t8);
    cudaGetSymbolAddress((void**)&q, g_q);
    cudaGetSymbolAddress((void**)&scores, g_scores);
    cudaGetSymbolAddress((void**)&wp, g_wp);
    cudaGetSymbolAddress((void**)&en, g_enorm);
    cudaGetSymbolAddress((void**)&scl, g_scale);
    cudaGetSymbolAddress((void**)&part, g_part);

    // ---- Encoder ----
    {
        GemmP p = mkP(x, enc_w1, enc_b1, nullptr, h16, nullptr, nullptr,
                      256, 48, 3, 32, 32, 16, 16, 2, 1, 1,
                      1, 0, 0, 16, 256, 1);
        conv_tc<4, 4, false><<<dim3(512, 2), 256>>>(p);
    }
    {
        GemmP p = mkP(h16, enc_w2, enc_b2, nullptr, h8, nullptr, nullptr,
                      256, 4096, 256, 16, 16, 8, 8, 2, 1, 1,
                      1, 0, 0, 8, 64, 1);
        conv_tc<4, 4, false><<<dim3(128, 2), 256>>>(p);
    }
    res_block(h8, t8, scl, rms_w + 0 * 32768, c3_w + 0 * 589824, c3_b + 0 * 256,
              c1_w + 0 * 65536, c1_b + 0 * 256);
    res_block(h8, t8, scl, rms_w + 1 * 32768, c3_w + 1 * 589824, c3_b + 1 * 256,
              c1_w + 1 * 65536, c1_b + 1 * 256);

    // ---- VQ (exact fp32 scores) ----
    enorm_kernel<<<2, 256>>>(emb, en);
    {
        GemmP p = mkP(h8, emb, nullptr, nullptr, scores, nullptr, nullptr,
                      512, 256, 256, 8, 8, 8, 8, 1, 0, 0,
                      1, 0, 0, 8, 64, 0);
        conv_gemm_simt<<<dim3(128, 4), 256>>>(p);
    }
    vq_argmin_kernel<<<2048, 256>>>(scores, en, emb, q);
    sqdiff_kernel<<<256, 256>>>(h8, q, part, 1048576);

    // ---- Decoder ----
    res_block(q, t8, scl, rms_w + 2 * 32768, c3_w + 2 * 589824, c3_b + 2 * 256,
              c1_w + 2 * 65536, c1_b + 2 * 256);
    res_block(q, t8, scl, rms_w + 3 * 32768, c3_w + 3 * 589824, c3_b + 3 * 256,
              c1_w + 3 * 65536, c1_b + 3 * 256);

    prep_wp_kernel<<<4096, 256>>>(dec_w1, wp);
    for (int par = 0; par < 4; par++) {
        int ph = par >> 1, pw = par & 1;
        GemmP p = mkP(q, wp + (size_t)par * 262144, dec_b1, nullptr, h16, nullptr, nullptr,
                      256, 1024, 256, 8, 8, 8, 8, 1, 1 - ph, 1 - pw,
                      2, ph, pw, 16, 256, 1);
        conv_tc<2, 2, false><<<dim3(128, 2), 256>>>(p);
    }

    deconv2_kernel<<<dim3(256, 4), 256>>>(h16, dec_w2, dec_b2, out + 4);

    sqdiff_kernel<<<256, 256>>>(out + 4, x, part + 256, 196608);
    finalize_kernel<<<1, 32>>>(part, part + 256, out);
}

// round 5
// speedup vs baseline: 1.8184x; 1.2625x over previous
#include <cuda_runtime.h>
#include <cstddef>

// ---------------------------------------------------------------------------
// VQ-VAE forward. Convs on tensor pipe via multi-term TF32 mma.sync.m16n8k8:
//   encoder: 3 terms (ah*bh + al*bh + ah*bl)  -> fp32-class (argmin safety)
//   decoder: 2 terms (ah*bh + al*bh)          -> ~1e-4, post-argmin only
// 2 CTAs/SM via __launch_bounds__(256,2) + per-mt fragment loading.
// VQ scores GEMM exact fp32 SIMT. Scratch in __device__ globals.
// ---------------------------------------------------------------------------

#define HS 256
#define NE 512

__device__ __align__(16) float g_h16[16777216];
__device__ __align__(16) float g_h8[4194304];
__device__ __align__(16) float g_t8[4194304];
__device__ __align__(16) float g_q[4194304];
__device__ __align__(16) float g_scores[8388608];
__device__ __align__(16) float g_wp[1048576];
__device__ __align__(16) float g_enorm[512];
__device__ __align__(16) float g_scale[256];
__device__ __align__(16) float g_part[512];

struct GemmP {
    const float* A; const float* W; const float* bias; const float* res; float* out;
    const float* ascale; const float* aweight;
    int N, K;
    int IC, IH, IW, OH, OW, stride, padh, padw;
    int oscale, ooffh, ooffw, oW, oHW;
    int mode;   // 0 plain, 1 bias+relu, 2 res+bias+relu
};

__device__ __forceinline__ unsigned f2tf32(float v) {
    unsigned u;
    asm("cvt.rna.tf32.f32 %0, %1;" : "=r"(u) : "f"(v));
    return u;
}

__device__ __forceinline__ void mma_tf32(float* d, const unsigned* a, const unsigned* b) {
    asm volatile(
        "mma.sync.aligned.m16n8k8.row.col.f32.tf32.tf32.f32 "
        "{%0,%1,%2,%3}, {%4,%5,%6,%7}, {%8,%9}, {%0,%1,%2,%3};"
        : "+f"(d[0]), "+f"(d[1]), "+f"(d[2]), "+f"(d[3])
        : "r"(a[0]), "r"(a[1]), "r"(a[2]), "r"(a[3]), "r"(b[0]), "r"(b[1]));
}

// ---------------------------------------------------------------------------
// Multi-term TF32 conv GEMM: 128x128 CTA, K-tile 16, warps 2(m)x4(n).
// NL = number of low-order correction passes: 3 => +al*bh +ah*bl; 2 => +al*bh.
// ---------------------------------------------------------------------------
template<int KH, int KW, bool RMS, int NL>
__global__ __launch_bounds__(256, 2) void conv_tc(GemmP p) {
    constexpr int KHKW = KH * KW;
    __shared__ unsigned Ah[16 * 136], Al[16 * 136];
    __shared__ unsigned Bh[16 * 136], Bl[16 * 136];
    __shared__ int sY[128], sX[128], sBase[128], sObase[128];
    __shared__ float sScl[128];

    const int tid = threadIdx.x;
    const int bm = blockIdx.x * 128;
    const int bn = blockIdx.y * 128;

    if (tid < 128) {
        int m = bm + tid;
        int ohw = p.OH * p.OW;
        int n = m / ohw;
        int rem = m - n * ohw;
        int oh = rem / p.OW;
        int ow = rem - oh * p.OW;
        sBase[tid] = n * p.IC * p.IH * p.IW;
        sY[tid] = oh * p.stride - p.padh;
        sX[tid] = ow * p.stride - p.padw;
        sObase[tid] = n * p.N * p.oHW + (oh * p.oscale + p.ooffh) * p.oW
                      + (ow * p.oscale + p.ooffw);
        sScl[tid] = RMS ? p.ascale[n] : 1.f;
    }
    __syncthreads();

    const int IH = p.IH, IW = p.IW;
    const int r = tid & 127;
    const int jset = (tid >> 7) * 8;
    const int rby = sY[r], rbx = sX[r], rbb = sBase[r];
    const float ascl = sScl[r];
    const int nb = tid & 127;
    const int kq = (tid >> 7) * 8;
    const float* Wrow = p.W + (size_t)(bn + nb) * p.K;

    const int w = tid >> 5, lane = tid & 31;
    const int wm = (w & 1) * 64, wn = (w >> 1) * 32;
    const int lg = lane >> 2, lk = lane & 3;

    float acc[4][4][4];
#pragma unroll
    for (int i = 0; i < 4; i++)
#pragma unroll
        for (int j = 0; j < 4; j++)
#pragma unroll
            for (int e = 0; e < 4; e++) acc[i][j][e] = 0.f;

    float avf[8];
    float bvf[8];

    auto gather = [&](int k0) {
#pragma unroll
        for (int q = 0; q < 8; q++) {
            int k = k0 + jset + q;
            int ic = k / KHKW;
            int kk2 = k - ic * KHKW;
            int kh = kk2 / KW;
            int kw = kk2 - kh * KW;
            int ih = rby + kh, iw = rbx + kw;
            float v = 0.f;
            if ((unsigned)ih < (unsigned)IH && (unsigned)iw < (unsigned)IW) {
                int ii = (ic * IH + ih) * IW + iw;
                v = p.A[rbb + ii];
                if (RMS) v *= ascl * p.aweight[ii];
            }
            avf[q] = v;
        }
        float4 b0 = *(const float4*)(Wrow + k0 + kq);
        float4 b1 = *(const float4*)(Wrow + k0 + kq + 4);
        bvf[0] = b0.x; bvf[1] = b0.y; bvf[2] = b0.z; bvf[3] = b0.w;
        bvf[4] = b1.x; bvf[5] = b1.y; bvf[6] = b1.z; bvf[7] = b1.w;
    };
    auto store = [&]() {
#pragma unroll
        for (int q = 0; q < 8; q++) {
            unsigned h = f2tf32(avf[q]);
            unsigned l = f2tf32(avf[q] - __uint_as_float(h));
            Ah[(jset + q) * 136 + r] = h;
            Al[(jset + q) * 136 + r] = l;
        }
#pragma unroll
        for (int q = 0; q < 8; q++) {
            unsigned h = f2tf32(bvf[q]);
            unsigned l = f2tf32(bvf[q] - __uint_as_float(h));
            Bh[(kq + q) * 136 + nb] = h;
            if (NL == 3) Bl[(kq + q) * 136 + nb] = l;
        }
    };

    const int ntiles = p.K >> 4;
    gather(0);
    for (int t = 0; t < ntiles; t++) {
        __syncthreads();
        store();
        __syncthreads();
        if (t + 1 < ntiles) gather((t + 1) << 4);
#pragma unroll
        for (int ks = 0; ks < 2; ks++) {
            const int k0 = ks * 8;
            unsigned bfh[4][2], bfl[4][2];
#pragma unroll
            for (int nt = 0; nt < 4; nt++) {
                int nl = wn + nt * 8 + lg;
                int i0 = (k0 + lk) * 136 + nl;
                int i1 = (k0 + lk + 4) * 136 + nl;
                bfh[nt][0] = Bh[i0];
                bfh[nt][1] = Bh[i1];
                if (NL == 3) { bfl[nt][0] = Bl[i0]; bfl[nt][1] = Bl[i1]; }
            }
#pragma unroll
            for (int mt = 0; mt < 4; mt++) {
                unsigned afh[4], afl[4];
                int ml = wm + mt * 16 + lg;
                int i0 = (k0 + lk) * 136 + ml;
                int i1 = (k0 + lk + 4) * 136 + ml;
                afh[0] = Ah[i0]; afh[1] = Ah[i0 + 8];
                afh[2] = Ah[i1]; afh[3] = Ah[i1 + 8];
                afl[0] = Al[i0]; afl[1] = Al[i0 + 8];
                afl[2] = Al[i1]; afl[3] = Al[i1 + 8];
#pragma unroll
                for (int nt = 0; nt < 4; nt++) {
                    mma_tf32(acc[mt][nt], afh, bfh[nt]);
                    mma_tf32(acc[mt][nt], afl, bfh[nt]);
                    if (NL == 3) mma_tf32(acc[mt][nt], afh, bfl[nt]);
                }
            }
        }
    }

    const int oHW = p.oHW;
#pragma unroll
    for (int mt = 0; mt < 4; mt++) {
#pragma unroll
        for (int half = 0; half < 2; half++) {
            int ml = wm + mt * 16 + lg + half * 8;
            int obase = sObase[ml];
#pragma unroll
            for (int nt = 0; nt < 4; nt++) {
                int oc = bn + wn + nt * 8 + lk * 2;
                float v0 = acc[mt][nt][half * 2 + 0];
                float v1 = acc[mt][nt][half * 2 + 1];
                if (p.bias) { v0 += p.bias[oc]; v1 += p.bias[oc + 1]; }
                if (p.mode >= 1) { v0 = fmaxf(v0, 0.f); v1 = fmaxf(v1, 0.f); }
                size_t oi0 = (size_t)obase + (size_t)oc * oHW;
                size_t oi1 = oi0 + oHW;
                if (p.mode == 2) { v0 += p.res[oi0]; v1 += p.res[oi1]; }
                p.out[oi0] = v0;
                p.out[oi1] = v1;
            }
        }
    }
}

// ---------------------------------------------------------------------------
// Exact fp32 SIMT GEMM (VQ scores, 1x1). 128x128 tile, 8x8/thread.
// ---------------------------------------------------------------------------
__global__ __launch_bounds__(256) void conv_gemm_simt(GemmP p) {
    __shared__ float As[2][16][128];
    __shared__ float Bs[2][16][128];
    __shared__ int sBase[128];

    const int tid = threadIdx.x;
    const int bm = blockIdx.x * 128;
    const int bn = blockIdx.y * 128;

    if (tid < 128) {
        int m = bm + tid;
        int ohw = p.OH * p.OW;
        int n = m / ohw;
        int rem = m - n * ohw;
        sBase[tid] = n * p.IC * p.IH * p.IW + rem;
    }
    __syncthreads();

    const int r = tid & 127;
    const int jset = (tid >> 7) * 8;
    const int rbb = sBase[r];
    const int nb = tid & 127;
    const int kq = (tid >> 7) * 8;
    const float* Wrow = p.W + (size_t)(bn + nb) * p.K;
    const int HWi = p.IH * p.IW;

    float av[8];
    float4 bv0, bv1;
    auto loadAB = [&](int k0) {
#pragma unroll
        for (int q = 0; q < 8; q++) {
            int ic = k0 + jset + q;
            av[q] = p.A[rbb + ic * HWi];
        }
        bv0 = *(const float4*)(Wrow + k0 + kq);
        bv1 = *(const float4*)(Wrow + k0 + kq + 4);
    };
    auto storeAB = [&](int buf) {
#pragma unroll
        for (int q = 0; q < 8; q++) As[buf][jset + q][r] = av[q];
        Bs[buf][kq + 0][nb] = bv0.x; Bs[buf][kq + 1][nb] = bv0.y;
        Bs[buf][kq + 2][nb] = bv0.z; Bs[buf][kq + 3][nb] = bv0.w;
        Bs[buf][kq + 4][nb] = bv1.x; Bs[buf][kq + 5][nb] = bv1.y;
        Bs[buf][kq + 6][nb] = bv1.z; Bs[buf][kq + 7][nb] = bv1.w;
    };

    const int tr = tid >> 4;
    const int tc = tid & 15;
    float acc[8][8];
#pragma unroll
    for (int i = 0; i < 8; i++)
#pragma unroll
        for (int j = 0; j < 8; j++) acc[i][j] = 0.f;

    const int nt = p.K >> 4;
    loadAB(0);
    storeAB(0);
    __syncthreads();
    for (int t = 0; t < nt; t++) {
        const int cur = t & 1;
        if (t + 1 < nt) loadAB((t + 1) << 4);
#pragma unroll
        for (int kk = 0; kk < 16; kk++) {
            float4 a0 = *(const float4*)&As[cur][kk][tr * 8];
            float4 a1 = *(const float4*)&As[cur][kk][tr * 8 + 4];
            float4 b0 = *(const float4*)&Bs[cur][kk][tc * 8];
            float4 b1 = *(const float4*)&Bs[cur][kk][tc * 8 + 4];
            float a[8] = {a0.x, a0.y, a0.z, a0.w, a1.x, a1.y, a1.z, a1.w};
            float b[8] = {b0.x, b0.y, b0.z, b0.w, b1.x, b1.y, b1.z, b1.w};
#pragma unroll
            for (int i = 0; i < 8; i++)
#pragma unroll
                for (int j = 0; j < 8; j++) acc[i][j] += a[i] * b[j];
        }
        if (t + 1 < nt) {
            storeAB(cur ^ 1);
            __syncthreads();
        }
    }

    const int ohw = p.OH * p.OW;
#pragma unroll
    for (int i = 0; i < 8; i++) {
        int m = bm + tr * 8 + i;
        int n = m / ohw;
        int rem = m - n * ohw;
        size_t obase = (size_t)n * p.N * p.oHW + rem;
#pragma unroll
        for (int j = 0; j < 8; j++) {
            int oc = bn + tc * 8 + j;
            p.out[obase + (size_t)oc * p.oHW] = acc[i][j];
        }
    }
}

// ---------------------------------------------------------------------------
__global__ __launch_bounds__(256) void rms_scale_kernel(const float* __restrict__ in,
                                                        float* __restrict__ scale) {
    const int n = blockIdx.x;
    const float4* xp = (const float4*)(in + (size_t)n * 16384);
    float s = 0.f;
    for (int i = threadIdx.x; i < 4096; i += 256) {
        float4 v = xp[i];
        s += v.x * v.x + v.y * v.y + v.z * v.z + v.w * v.w;
    }
    __shared__ float sh[256];
    sh[threadIdx.x] = s;
    __syncthreads();
    for (int st = 128; st > 0; st >>= 1) {
        if (threadIdx.x < st) sh[threadIdx.x] += sh[threadIdx.x + st];
        __syncthreads();
    }
    if (threadIdx.x == 0)
        scale[n] = rsqrtf(sh[0] * (1.f / 16384.f) + 1.1920929e-07f);
}

__global__ void enorm_kernel(const float* __restrict__ e, float* __restrict__ en) {
    int j = blockIdx.x * 256 + threadIdx.x;
    if (j >= NE) return;
    const float* r = e + (size_t)j * HS;
    float s = 0.f;
    for (int c = 0; c < HS; c++) { float v = r[c]; s += v * v; }
    en[j] = s;
}

__global__ __launch_bounds__(256) void vq_argmin_kernel(const float* __restrict__ scores,
                                                        const float* __restrict__ en,
                                                        const float* __restrict__ emb,
                                                        float* __restrict__ q) {
    int token = blockIdx.x * 8 + (threadIdx.x >> 5);
    int lane = threadIdx.x & 31;
    int n = token >> 6, hw = token & 63;
    const float* sc = scores + ((size_t)n * NE) * 64 + hw;
    float best = 3.4e38f;
    int bj = NE;
    for (int j = lane; j < NE; j += 32) {
        float d = en[j] - 2.f * sc[(size_t)j * 64];
        if (d < best || (d == best && j < bj)) { best = d; bj = j; }
    }
#pragma unroll
    for (int off = 16; off; off >>= 1) {
        float ob = __shfl_down_sync(0xffffffffu, best, off);
        int oj = __shfl_down_sync(0xffffffffu, bj, off);
        if (ob < best || (ob == best && oj < bj)) { best = ob; bj = oj; }
    }
    bj = __shfl_sync(0xffffffffu, bj, 0);
    const float* er = emb + (size_t)bj * HS;
    float* qp = q + (size_t)n * HS * 64 + hw;
    for (int c = lane; c < HS; c += 32) qp[(size_t)c * 64] = er[c];
}

__global__ __launch_bounds__(256) void sqdiff_kernel(const float* __restrict__ a,
                                                     const float* __restrict__ b,
                                                     float* __restrict__ part, int nvec4) {
    const float4* a4 = (const float4*)a;
    const float4* b4 = (const float4*)b;
    float s = 0.f;
    for (int i = blockIdx.x * 256 + threadIdx.x; i < nvec4; i += 256 * 256) {
        float4 va = a4[i], vb = b4[i];
        float dx = va.x - vb.x, dy = va.y - vb.y, dz = va.z - vb.z, dw = va.w - vb.w;
        s += dx * dx + dy * dy + dz * dz + dw * dw;
    }
    __shared__ float sh[256];
    sh[threadIdx.x] = s;
    __syncthreads();
    for (int st = 128; st > 0; st >>= 1) {
        if (threadIdx.x < st) sh[threadIdx.x] += sh[threadIdx.x + st];
        __syncthreads();
    }
    if (threadIdx.x == 0) part[blockIdx.x] = sh[0];
}

__global__ void finalize_kernel(const float* __restrict__ partVq,
                                const float* __restrict__ partRec,
                                float* __restrict__ out) {
    if (threadIdx.x == 0 && blockIdx.x == 0) {
        float svq = 0.f, sre = 0.f;
        for (int i = 0; i < 256; i++) { svq += partVq[i]; sre += partRec[i]; }
        float dict = svq * (1.f / 4194304.f);
        float rec = sre * (1.f / 786432.f);
        out[0] = rec + dict + dict;
        out[1] = rec;
        out[2] = dict;
        out[3] = dict;
    }
}

__global__ void prep_wp_kernel(const float* __restrict__ w, float* __restrict__ wp) {
    int idx = blockIdx.x * 256 + threadIdx.x;
    if (idx >= 1048576) return;
    int b = idx & 1;
    int a = (idx >> 1) & 1;
    int ic = (idx >> 2) & 255;
    int oc = (idx >> 10) & 255;
    int p = idx >> 18;
    int ph = p >> 1, pw = p & 1;
    int kh = ph + 2 * a, kw = pw + 2 * b;
    wp[idx] = w[((size_t)(ic * 256 + oc) * 4 + (3 - kh)) * 4 + (3 - kw)];
}

__global__ __launch_bounds__(256) void deconv2_kernel(const float* __restrict__ in,
                                                      const float* __restrict__ w,
                                                      const float* __restrict__ bias,
                                                      float* __restrict__ out) {
    __shared__ float wsh[4 * 256 * 3];
    const int n = blockIdx.x;
    const int par = blockIdx.y;
    const int ph = par >> 1, pw = par & 1;
    const int tid = threadIdx.x;

    for (int idx = tid; idx < 3072; idx += 256) {
        int oc = idx % 3;
        int rest = idx / 3;
        int ic = rest & 255;
        int t = rest >> 8;
        int a = t >> 1, b = t & 1;
        int kh = ph + 2 * a, kw = pw + 2 * b;
        wsh[idx] = w[((size_t)(ic * 3 + oc) * 4 + (3 - kh)) * 4 + (3 - kw)];
    }
    __syncthreads();

    const int i = tid >> 4, j = tid & 15;
    const int oh = 2 * i + ph, ow = 2 * j + pw;
    float acc0 = 0.f, acc1 = 0.f, acc2 = 0.f;

    int base[4];
    bool ok[4];
#pragma unroll
    for (int t = 0; t < 4; t++) {
        int a = t >> 1, b = t & 1;
        int ih = i + ph + a - 1, iw = j + pw + b - 1;
        ok[t] = ((unsigned)ih < 16u) && ((unsigned)iw < 16u);
        base[t] = ok[t] ? (n * 65536 + ih * 16 + iw) : 0;
    }
    for (int ic = 0; ic < 256; ic++) {
        int ico = ic * 256;
#pragma unroll
        for (int t = 0; t < 4; t++) {
            if (ok[t]) {
                float v = in[base[t] + ico];
                const float* wp2 = &wsh[(t * 256 + ic) * 3];
                acc0 += v * wp2[0];
                acc1 += v * wp2[1];
                acc2 += v * wp2[2];
            }
        }
    }
    size_t o = (size_t)n * 3072 + (size_t)oh * 32 + ow;
    out[o] = acc0 + bias[0];
    out[o + 1024] = acc1 + bias[1];
    out[o + 2048] = acc2 + bias[2];
}

// ---------------------------------------------------------------------------
static GemmP mkP(const float* A, const float* W, const float* bias, const float* res,
                 float* out, const float* ascale, const float* aweight,
                 int N, int K, int IC, int IH, int IW, int OH, int OW,
                 int stride, int padh, int padw,
                 int oscale, int ooffh, int ooffw, int oW, int oHW, int mode) {
    GemmP p;
    p.A = A; p.W = W; p.bias = bias; p.res = res; p.out = out;
    p.ascale = ascale; p.aweight = aweight;
    p.N = N; p.K = K; p.IC = IC; p.IH = IH; p.IW = IW; p.OH = OH; p.OW = OW;
    p.stride = stride; p.padh = padh; p.padw = padw;
    p.oscale = oscale; p.ooffh = ooffh; p.ooffw = ooffw; p.oW = oW; p.oHW = oHW;
    p.mode = mode;
    return p;
}

template<int NL>
static void res_block(float* x, float* tmp, float* scl, const float* rmsw,
                      const float* w3, const float* b3,
                      const float* w1, const float* b1) {
    rms_scale_kernel<<<256, 256>>>(x, scl);
    {
        GemmP p = mkP(x, w3, b3, x, tmp, scl, rmsw,
                      256, 2304, 256, 8, 8, 8, 8, 1, 1, 1,
                      1, 0, 0, 8, 64, 2);
        conv_tc<3, 3, true, NL><<<dim3(128, 2), 256>>>(p);
    }
    rms_scale_kernel<<<256, 256>>>(tmp, scl);
    {
        GemmP p = mkP(tmp, w1, b1, tmp, x, scl, rmsw + 16384,
                      256, 256, 256, 8, 8, 8, 8, 1, 0, 0,
                      1, 0, 0, 8, 64, 2);
        conv_tc<1, 1, true, NL><<<dim3(128, 2), 256>>>(p);
    }
}

extern "C" void kernel_launch(void* const* d_in, const int* in_sizes, int n_in,
                              void* d_out, int out_size) {
    const float* x       = (const float*)d_in[0];
    const float* enc_w1  = (const float*)d_in[1];
    const float* enc_b1  = (const float*)d_in[2];
    const float* enc_w2  = (const float*)d_in[3];
    const float* enc_b2  = (const float*)d_in[4];
    const float* rms_w   = (const float*)d_in[5];
    const float* c3_w    = (const float*)d_in[6];
    const float* c3_b    = (const float*)d_in[7];
    const float* c1_w    = (const float*)d_in[8];
    const float* c1_b    = (const float*)d_in[9];
    const float* emb     = (const float*)d_in[10];
    const float* dec_w1  = (const float*)d_in[11];
    const float* dec_b1  = (const float*)d_in[12];
    const float* dec_w2  = (const float*)d_in[13];
    const float* dec_b2  = (const float*)d_in[14];
    float* out = (float*)d_out;

    float *h16, *h8, *t8, *q, *scores, *wp, *en, *scl, *part;
    cudaGetSymbolAddress((void**)&h16, g_h16);
    cudaGetSymbolAddress((void**)&h8, g_h8);
    cudaGetSymbolAddress((void**)&t8, g_t8);
    cudaGetSymbolAddress((void**)&q, g_q);
    cudaGetSymbolAddress((void**)&scores, g_scores);
    cudaGetSymbolAddress((void**)&wp, g_wp);
    cudaGetSymbolAddress((void**)&en, g_enorm);
    cudaGetSymbolAddress((void**)&scl, g_scale);
    cudaGetSymbolAddress((void**)&part, g_part);

    // ---- Encoder (3-term TF32: protects VQ argmin) ----
    {
        GemmP p = mkP(x, enc_w1, enc_b1, nullptr, h16, nullptr, nullptr,
                      256, 48, 3, 32, 32, 16, 16, 2, 1, 1,
                      1, 0, 0, 16, 256, 1);
        conv_tc<4, 4, false, 3><<<dim3(512, 2), 256>>>(p);
    }
    {
        GemmP p = mkP(h16, enc_w2, enc_b2, nullptr, h8, nullptr, nullptr,
                      256, 4096, 256, 16, 16, 8, 8, 2, 1, 1,
                      1, 0, 0, 8, 64, 1);
        conv_tc<4, 4, false, 3><<<dim3(128, 2), 256>>>(p);
    }
    res_block<3>(h8, t8, scl, rms_w + 0 * 32768, c3_w + 0 * 589824, c3_b + 0 * 256,
                 c1_w + 0 * 65536, c1_b + 0 * 256);
    res_block<3>(h8, t8, scl, rms_w + 1 * 32768, c3_w + 1 * 589824, c3_b + 1 * 256,
                 c1_w + 1 * 65536, c1_b + 1 * 256);

    // ---- VQ (exact fp32 scores) ----
    enorm_kernel<<<2, 256>>>(emb, en);
    {
        GemmP p = mkP(h8, emb, nullptr, nullptr, scores, nullptr, nullptr,
                      512, 256, 256, 8, 8, 8, 8, 1, 0, 0,
                      1, 0, 0, 8, 64, 0);
        conv_gemm_simt<<<dim3(128, 4), 256>>>(p);
    }
    vq_argmin_kernel<<<2048, 256>>>(scores, en, emb, q);
    sqdiff_kernel<<<256, 256>>>(h8, q, part, 1048576);

    // ---- Decoder (2-term TF32: post-argmin, ~1e-4 ok) ----
    res_block<2>(q, t8, scl, rms_w + 2 * 32768, c3_w + 2 * 589824, c3_b + 2 * 256,
                 c1_w + 2 * 65536, c1_b + 2 * 256);
    res_block<2>(q, t8, scl, rms_w + 3 * 32768, c3_w + 3 * 589824, c3_b + 3 * 256,
                 c1_w + 3 * 65536, c1_b + 3 * 256);

    prep_wp_kernel<<<4096, 256>>>(dec_w1, wp);
    for (int par = 0; par < 4; par++) {
        int ph = par >> 1, pw = par & 1;
        GemmP p = mkP(q, wp + (size_t)par * 262144, dec_b1, nullptr, h16, nullptr, nullptr,
                      256, 1024, 256, 8, 8, 8, 8, 1, 1 - ph, 1 - pw,
                      2, ph, pw, 16, 256, 1);
        conv_tc<2, 2, false, 2><<<dim3(128, 2), 256>>>(p);
    }

    deconv2_kernel<<<dim3(256, 4), 256>>>(h16, dec_w2, dec_b2, out + 4);

    sqdiff_kernel<<<256, 256>>>(out + 4, x, part + 256, 196608);
    finalize_kernel<<<1, 32>>>(part, part + 256, out);
}